// round 1
// baseline (speedup 1.0000x reference)
#include <cuda_runtime.h>
#include <math.h>

#define B_      8
#define K_      256
#define DIM_    50257
#define KNN_    8
#define NCLASS_ 4
// scaled = (-1/KNN_T) * mean = sum * (-1/(0.05*DIM))
#define SCALE_  (-1.0f / (0.05f * (float)DIM_))

// Scratch (no allocations allowed in kernel_launch)
__device__ float g_ll[B_ * DIM_];   // log(logits)
__device__ float g_sd[B_ * K_];     // scaled dists

// ---------------------------------------------------------------------------
// Kernel 1: accurate log of logits (tiny: 402K elements)
// ---------------------------------------------------------------------------
__global__ void k_log(const float* __restrict__ logits) {
    int i = blockIdx.x * blockDim.x + threadIdx.x;
    if (i < B_ * DIM_) g_ll[i] = logf(logits[i]);
}

// ---------------------------------------------------------------------------
// Fast log for x in [1e-3, 1]: exponent extraction + deg-8 log1p Taylor.
// Abs error ~4e-5; averaged over 50257 elements per (b,k) the k-to-k
// variation is ~1e-7 and the common bias cancels in softmax.
// ---------------------------------------------------------------------------
__device__ __forceinline__ float fastlog(float x) {
    int ix = __float_as_int(x);
    int j  = ix - 0x3f350000;          // center mantissa near 1 (sqrt(2)/2 split)
    int kk = j >> 23;                  // unbiased exponent adjustment
    float m = __int_as_float(ix - (kk << 23));   // m in [0.7070, 1.4141)
    float e = (float)kk;
    float t = m - 1.0f;                // t in [-0.293, 0.414]
    float z = t * t;
    // P(t) = 1/3 - t/4 + t^2/5 - t^3/6 + t^4/7 - t^5/8
    float p = -0.125f;
    p = fmaf(p, t,  0.14285714f);
    p = fmaf(p, t, -0.16666667f);
    p = fmaf(p, t,  0.2f);
    p = fmaf(p, t, -0.25f);
    p = fmaf(p, t,  0.33333333f);
    // log(1+t) = t - z/2 + t*z*P(t)
    float y = fmaf(t * z, p, fmaf(-0.5f, z, t));
    return fmaf(e, 0.69314718f, y);
}

// ---------------------------------------------------------------------------
// Kernel 2: dists for a pair of k rows per block (shares log_logits loads).
// grid = B*K/2 blocks, 256 threads.
// ---------------------------------------------------------------------------
__global__ void __launch_bounds__(256) k_dist(const float* __restrict__ qa) {
    const int pair = blockIdx.x;                 // 0 .. B*K/2-1
    const int b    = pair / (K_ / 2);
    const int k0   = (pair % (K_ / 2)) * 2;

    const float* __restrict__ ll = g_ll + (size_t)b * DIM_;
    const float* __restrict__ q0 = qa + ((size_t)(b * K_ + k0)) * DIM_;
    const float* __restrict__ q1 = q0 + DIM_;

    float a0 = 0.0f, a1 = 0.0f;
    #pragma unroll 4
    for (int d = threadIdx.x; d < DIM_; d += 256) {
        float l  = __ldg(ll + d);
        float x0 = __ldg(q0 + d);
        float x1 = __ldg(q1 + d);
        a0 = fmaf(x0, fastlog(x0) - l, a0);
        a1 = fmaf(x1, fastlog(x1) - l, a1);
    }

    // Block reduction: warp shuffle then cross-warp via shared.
    #pragma unroll
    for (int s = 16; s > 0; s >>= 1) {
        a0 += __shfl_xor_sync(0xFFFFFFFFu, a0, s);
        a1 += __shfl_xor_sync(0xFFFFFFFFu, a1, s);
    }
    __shared__ float s0[8], s1[8];
    const int wid = threadIdx.x >> 5;
    const int lid = threadIdx.x & 31;
    if (lid == 0) { s0[wid] = a0; s1[wid] = a1; }
    __syncthreads();
    if (threadIdx.x == 0) {
        float t0 = 0.0f, t1 = 0.0f;
        #pragma unroll
        for (int w = 0; w < 8; w++) { t0 += s0[w]; t1 += s1[w]; }
        g_sd[b * K_ + k0]     = t0 * SCALE_;
        g_sd[b * K_ + k0 + 1] = t1 * SCALE_;
    }
}

// ---------------------------------------------------------------------------
// Kernel 3: per-b top-8 (jax tie-break: lowest index), softmax, class scatter.
// grid = B blocks, 256 threads (thread t owns k=t).
// ---------------------------------------------------------------------------
__global__ void __launch_bounds__(256) k_topk(const int* __restrict__ qlabel,
                                              float* __restrict__ out) {
    const int b = blockIdx.x;
    const int t = threadIdx.x;

    __shared__ float sv[K_];
    __shared__ float rv[K_];
    __shared__ int   ri[K_];
    __shared__ float topv[KNN_];
    __shared__ int   topi[KNN_];

    sv[t] = g_sd[b * K_ + t];
    __syncthreads();

    for (int r = 0; r < KNN_; r++) {
        rv[t] = sv[t];
        ri[t] = t;
        __syncthreads();
        #pragma unroll
        for (int s = 128; s > 0; s >>= 1) {
            if (t < s) {
                float v2 = rv[t + s]; int i2 = ri[t + s];
                if (v2 > rv[t] || (v2 == rv[t] && i2 < ri[t])) {
                    rv[t] = v2; ri[t] = i2;
                }
            }
            __syncthreads();
        }
        if (t == 0) {
            topv[r] = rv[0];
            topi[r] = ri[0];
            sv[ri[0]] = -INFINITY;   // remove winner for next round
        }
        __syncthreads();
    }

    if (t == 0) {
        float mx = topv[0];          // sorted descending: [0] is max
        float w[KNN_];
        float sum = 0.0f;
        #pragma unroll
        for (int r = 0; r < KNN_; r++) { w[r] = expf(topv[r] - mx); sum += w[r]; }
        float inv = 1.0f / sum;
        float o[NCLASS_] = {0.0f, 0.0f, 0.0f, 0.0f};
        #pragma unroll
        for (int r = 0; r < KNN_; r++) {
            int c = qlabel[b * K_ + topi[r]];
            o[c] += w[r] * inv;
        }
        #pragma unroll
        for (int c = 0; c < NCLASS_; c++) out[b * NCLASS_ + c] = o[c];
    }
}

// ---------------------------------------------------------------------------
// Launch
// ---------------------------------------------------------------------------
extern "C" void kernel_launch(void* const* d_in, const int* in_sizes, int n_in,
                              void* d_out, int out_size) {
    // Robust input identification by element count.
    const float* logits = nullptr;
    const float* qa     = nullptr;
    const int*   qlabel = nullptr;
    for (int i = 0; i < n_in; i++) {
        if (in_sizes[i] == B_ * DIM_)               logits = (const float*)d_in[i];
        else if (in_sizes[i] == B_ * K_ * DIM_)     qa     = (const float*)d_in[i];
        else if (in_sizes[i] == B_ * K_)            qlabel = (const int*)d_in[i];
    }
    float* out = (float*)d_out;

    k_log <<<(B_ * DIM_ + 255) / 256, 256>>>(logits);
    k_dist<<<B_ * K_ / 2, 256>>>(qa);
    k_topk<<<B_, 256>>>(qlabel, out);
}

// round 2
// speedup vs baseline: 1.0898x; 1.0898x over previous
#include <cuda_runtime.h>
#include <math.h>

#define B_      8
#define K_      256
#define DIM_    50257
#define KNN_    8
#define NCLASS_ 4
#define SCALE_  (-1.0f / (0.05f * (float)DIM_))

typedef unsigned long long u64;

__device__ float g_ll[B_ * DIM_];   // log(logits)
__device__ float g_sd[B_ * K_];     // scaled dists

// ---------------------------------------------------------------------------
// Packed f32x2 helpers (sm_103a FFMA2 path — ptxas never auto-fuses these)
// ---------------------------------------------------------------------------
__device__ __forceinline__ u64 pk(float lo, float hi) {
    u64 r; asm("mov.b64 %0, {%1, %2};" : "=l"(r) : "f"(lo), "f"(hi)); return r;
}
__device__ __forceinline__ u64 bcast(float c) {
    unsigned u = __float_as_uint(c); return ((u64)u << 32) | (u64)u;
}
__device__ __forceinline__ void unpk(u64 v, float& lo, float& hi) {
    asm("mov.b64 {%0, %1}, %2;" : "=f"(lo), "=f"(hi) : "l"(v));
}
__device__ __forceinline__ u64 fma2(u64 a, u64 b, u64 c) {
    u64 d; asm("fma.rn.f32x2 %0, %1, %2, %3;" : "=l"(d) : "l"(a), "l"(b), "l"(c)); return d;
}
__device__ __forceinline__ u64 mul2(u64 a, u64 b) {
    u64 d; asm("mul.rn.f32x2 %0, %1, %2;" : "=l"(d) : "l"(a), "l"(b)); return d;
}
__device__ __forceinline__ u64 add2(u64 a, u64 b) {
    u64 d; asm("add.rn.f32x2 %0, %1, %2;" : "=l"(d) : "l"(a), "l"(b)); return d;
}

// ---------------------------------------------------------------------------
// Kernel 1: accurate log of logits — float4 (402056 elems, divisible by 4)
// ---------------------------------------------------------------------------
__global__ void k_log(const float* __restrict__ logits) {
    int i = blockIdx.x * blockDim.x + threadIdx.x;
    if (i < (B_ * DIM_) / 4) {
        float4 x = ((const float4*)logits)[i];
        float4 y;
        y.x = logf(x.x); y.y = logf(x.y); y.z = logf(x.z); y.w = logf(x.w);
        ((float4*)g_ll)[i] = y;
    }
}

// ---------------------------------------------------------------------------
// Packed fast log for the (x0, x1) row-pair at one d.
// Exponent extraction scalar (alu pipe), polynomial packed (fma pipe).
// x in [1e-3, 1]; abs err ~4e-5, averaged over 50257 d's per (b,k).
// ---------------------------------------------------------------------------
__device__ __forceinline__ u64 fastlog2pk(float x0, float x1) {
    int i0 = __float_as_int(x0), i1 = __float_as_int(x1);
    int k0 = (i0 - 0x3f350000) >> 23;
    int k1 = (i1 - 0x3f350000) >> 23;
    float m0 = __int_as_float(i0 - (k0 << 23));   // [0.707, 1.414)
    float m1 = __int_as_float(i1 - (k1 << 23));
    u64 e = pk((float)k0, (float)k1);
    u64 t = add2(pk(m0, m1), bcast(-1.0f));       // t in [-0.293, 0.414]
    u64 z = mul2(t, t);
    u64 p = bcast(-0.125f);
    p = fma2(p, t, bcast( 0.14285714f));
    p = fma2(p, t, bcast(-0.16666667f));
    p = fma2(p, t, bcast( 0.2f));
    p = fma2(p, t, bcast(-0.25f));
    p = fma2(p, t, bcast( 0.33333333f));
    // log(1+t) = t - z/2 + t*z*P(t)
    u64 y = fma2(mul2(t, z), p, fma2(bcast(-0.5f), z, t));
    return fma2(e, bcast(0.69314718f), y);
}

// ---------------------------------------------------------------------------
// Kernel 2: dists for a pair of k rows per block (shared log_logits load).
// All fp math packed f32x2; two independent accumulator chains.
// ---------------------------------------------------------------------------
__global__ void __launch_bounds__(256) k_dist(const float* __restrict__ qa) {
    const int pair = blockIdx.x;            // 0 .. B*K/2-1
    const int b    = pair >> 7;             // / 128
    const int k0   = (pair & 127) * 2;

    const float* __restrict__ ll = g_ll + (size_t)b * DIM_;
    const float* __restrict__ q0 = qa + ((size_t)(b * K_ + k0)) * DIM_;
    const float* __restrict__ q1 = q0 + DIM_;

    const u64 NEG1 = bcast(-1.0f);
    u64 acc0 = 0ull, acc1 = 0ull;

    int d = threadIdx.x;
    #pragma unroll 2
    for (; d + 256 < DIM_; d += 512) {
        {
            float l  = __ldg(ll + d);
            float x0 = __ldg(q0 + d);
            float x1 = __ldg(q1 + d);
            u64 diff = fma2(pk(l, l), NEG1, fastlog2pk(x0, x1));  // log x - log l
            acc0 = fma2(pk(x0, x1), diff, acc0);
        }
        {
            int e2 = d + 256;
            float l  = __ldg(ll + e2);
            float x0 = __ldg(q0 + e2);
            float x1 = __ldg(q1 + e2);
            u64 diff = fma2(pk(l, l), NEG1, fastlog2pk(x0, x1));
            acc1 = fma2(pk(x0, x1), diff, acc1);
        }
    }
    for (; d < DIM_; d += 256) {
        float l  = __ldg(ll + d);
        float x0 = __ldg(q0 + d);
        float x1 = __ldg(q1 + d);
        u64 diff = fma2(pk(l, l), NEG1, fastlog2pk(x0, x1));
        acc0 = fma2(pk(x0, x1), diff, acc0);
    }

    float a0, a1;
    unpk(add2(acc0, acc1), a0, a1);

    #pragma unroll
    for (int s = 16; s > 0; s >>= 1) {
        a0 += __shfl_xor_sync(0xFFFFFFFFu, a0, s);
        a1 += __shfl_xor_sync(0xFFFFFFFFu, a1, s);
    }
    __shared__ float s0[8], s1[8];
    const int wid = threadIdx.x >> 5;
    const int lid = threadIdx.x & 31;
    if (lid == 0) { s0[wid] = a0; s1[wid] = a1; }
    __syncthreads();
    if (threadIdx.x == 0) {
        float t0 = 0.0f, t1 = 0.0f;
        #pragma unroll
        for (int w = 0; w < 8; w++) { t0 += s0[w]; t1 += s1[w]; }
        g_sd[b * K_ + k0]     = t0 * SCALE_;
        g_sd[b * K_ + k0 + 1] = t1 * SCALE_;
    }
}

// ---------------------------------------------------------------------------
// Kernel 3: one block, warp w handles batch b=w. Warp-shuffle top-8
// (value max, tie -> lowest index, matching jax top_k), softmax, scatter.
// ---------------------------------------------------------------------------
__global__ void __launch_bounds__(256) k_topk(const int* __restrict__ qlabel,
                                              float* __restrict__ out) {
    const int w    = threadIdx.x >> 5;      // b
    const int lane = threadIdx.x & 31;

    float v[8];
    #pragma unroll
    for (int j = 0; j < 8; j++) v[j] = g_sd[w * K_ + j * 32 + lane];

    float topv[KNN_];
    int   topi[KNN_];
    #pragma unroll
    for (int r = 0; r < KNN_; r++) {
        float bv = -INFINITY; int bi = K_;
        #pragma unroll
        for (int j = 0; j < 8; j++) {
            int idx = j * 32 + lane;
            if (v[j] > bv) { bv = v[j]; bi = idx; }   // strict > keeps lowest idx
        }
        #pragma unroll
        for (int s = 16; s > 0; s >>= 1) {
            float ov = __shfl_xor_sync(0xFFFFFFFFu, bv, s);
            int   oi = __shfl_xor_sync(0xFFFFFFFFu, bi, s);
            if (ov > bv || (ov == bv && oi < bi)) { bv = ov; bi = oi; }
        }
        topv[r] = bv; topi[r] = bi;
        if ((bi & 31) == lane) v[bi >> 5] = -INFINITY;  // remove winner
    }

    if (lane == 0) {
        float mx = topv[0];                 // rounds are descending
        float wt[KNN_], sum = 0.0f;
        #pragma unroll
        for (int r = 0; r < KNN_; r++) { wt[r] = expf(topv[r] - mx); sum += wt[r]; }
        float inv = 1.0f / sum;
        float o[NCLASS_] = {0.0f, 0.0f, 0.0f, 0.0f};
        #pragma unroll
        for (int r = 0; r < KNN_; r++)
            o[qlabel[w * K_ + topi[r]]] += wt[r] * inv;
        #pragma unroll
        for (int c = 0; c < NCLASS_; c++) out[w * NCLASS_ + c] = o[c];
    }
}

// ---------------------------------------------------------------------------
// Launch
// ---------------------------------------------------------------------------
extern "C" void kernel_launch(void* const* d_in, const int* in_sizes, int n_in,
                              void* d_out, int out_size) {
    const float* logits = nullptr;
    const float* qa     = nullptr;
    const int*   qlabel = nullptr;
    for (int i = 0; i < n_in; i++) {
        if (in_sizes[i] == B_ * DIM_)           logits = (const float*)d_in[i];
        else if (in_sizes[i] == B_ * K_ * DIM_) qa     = (const float*)d_in[i];
        else if (in_sizes[i] == B_ * K_)        qlabel = (const int*)d_in[i];
    }
    float* out = (float*)d_out;

    k_log <<<((B_ * DIM_) / 4 + 255) / 256, 256>>>(logits);
    k_dist<<<B_ * K_ / 2, 256>>>(qa);
    k_topk<<<1, 256>>>(qlabel, out);
}